// round 7
// baseline (speedup 1.0000x reference)
#include <cuda_runtime.h>
#include <cstdint>

#define L  2
#define T  128
#define NB 64      // batch N
#define H  512
#define E  256
#define A  200
#define V  1000
#define S  40
#define LT (L*T)   // 256
#define KIN0 (E+H) // 768

// ---------------- scratch (device globals) ----------------
__device__ __align__(16) float g_Kproj[L*T*NB*A];    // (l,t,n,a)
__device__ __align__(16) float g_qproj[L*NB*A];      // (l,n,a)
__device__ __align__(16) float g_scores[NB*LT];      // (n, lt)
__device__ __align__(16) float g_x[(E+H)*NB];        // (k,n)
__device__ __align__(16) float g_h[2][L][H*NB];      // [pingpong][layer][(k,n)]
__device__ __align__(16) float g_proj[H*NB];         // (k,n)
__device__ unsigned g_bar_count;
__device__ volatile unsigned g_bar_gen;

// ---------------- grid barrier (all blocks resident: grid == #SMs, 1 blk/SM) ----
__device__ __forceinline__ void grid_sync(int nb) {
    __syncthreads();
    if (threadIdx.x == 0) {
        __threadfence();
        unsigned gen = g_bar_gen;
        unsigned arrived = atomicAdd(&g_bar_count, 1u);
        if (arrived == (unsigned)nb - 1u) {
            g_bar_count = 0u;
            __threadfence();
            g_bar_gen = gen + 1u;
        } else {
            while (g_bar_gen == gen) { __nanosleep(32); }
        }
        __threadfence();
    }
    __syncthreads();
}

// ---------------- MUFU-free fast math ----------------
__device__ __forceinline__ float fast_rcp(float q) {
    float r = __uint_as_float(0x7EF311C3u - __float_as_uint(q));
    r = r * (2.0f - q * r);
    r = r * (2.0f - q * r);
    r = r * (2.0f - q * r);
    return r;
}

__device__ __forceinline__ float tanh_fast(float x) {
    const float c = 7.99881172180175781f;
    x = fminf(fmaxf(x, -c), c);
    float x2 = x * x;
    float p = fmaf(x2, -2.76076847742355e-16f, 2.00018790482477e-13f);
    p = fmaf(x2, p, -8.60467152213735e-11f);
    p = fmaf(x2, p,  5.12229709037114e-08f);
    p = fmaf(x2, p,  1.48572235717979e-05f);
    p = fmaf(x2, p,  6.37261928875436e-04f);
    p = fmaf(x2, p,  4.89352455891786e-03f);
    p = p * x;
    float q = fmaf(x2, 1.19825839466702e-06f, 1.18534705686654e-04f);
    q = fmaf(x2, q, 2.26843463243900e-03f);
    q = fmaf(x2, q, 4.89352518554385e-03f);
    return p * fast_rcp(q);
}

__device__ __forceinline__ float sigmoid_fast(float x) {
    return fmaf(tanh_fast(0.5f * x), 0.5f, 0.5f);
}

// ---------------- prep kernels ----------------
__global__ void prep_hinit(const float* __restrict__ efs) {
    int i = blockIdx.x * 256 + threadIdx.x;        // over L*NB*H
    if (i >= L * NB * H) return;
    int k = i % H;
    int n = (i / H) % NB;
    int l = i / (NB * H);
    g_h[0][l][k * NB + n] = efs[i];
}

__global__ void kproj_gemm(const float* __restrict__ eo,
                           const float* __restrict__ Kw,
                           const float* __restrict__ Kb) {
    const int l   = blockIdx.z;
    const int tn0 = blockIdx.x * 64;
    const int a0  = blockIdx.y * 64;
    const float* Ab = eo + (size_t)l * (T * NB) * H;
    const float* Bb = Kw + (size_t)l * A * H;
    __shared__ float As[16][64];
    __shared__ float Bs[16][64];
    const int tid = threadIdx.x;
    const int tr = tid >> 4, tc = tid & 15;
    const int lr = tid >> 2;
    const int lk = (tid & 3) * 4;
    float acc[4][4];
    #pragma unroll
    for (int i = 0; i < 4; i++)
        #pragma unroll
        for (int j = 0; j < 4; j++) acc[i][j] = 0.0f;

    for (int k0 = 0; k0 < H; k0 += 16) {
        float4 a4 = *reinterpret_cast<const float4*>(&Ab[(size_t)(tn0 + lr) * H + k0 + lk]);
        As[lk + 0][lr] = a4.x; As[lk + 1][lr] = a4.y;
        As[lk + 2][lr] = a4.z; As[lk + 3][lr] = a4.w;
        float4 b4 = make_float4(0.f, 0.f, 0.f, 0.f);
        if (a0 + lr < A)
            b4 = *reinterpret_cast<const float4*>(&Bb[(size_t)(a0 + lr) * H + k0 + lk]);
        Bs[lk + 0][lr] = b4.x; Bs[lk + 1][lr] = b4.y;
        Bs[lk + 2][lr] = b4.z; Bs[lk + 3][lr] = b4.w;
        __syncthreads();
        #pragma unroll
        for (int kk = 0; kk < 16; kk++) {
            float4 av = *reinterpret_cast<const float4*>(&As[kk][tr * 4]);
            float4 bv = *reinterpret_cast<const float4*>(&Bs[kk][tc * 4]);
            acc[0][0]=fmaf(av.x,bv.x,acc[0][0]); acc[0][1]=fmaf(av.x,bv.y,acc[0][1]);
            acc[0][2]=fmaf(av.x,bv.z,acc[0][2]); acc[0][3]=fmaf(av.x,bv.w,acc[0][3]);
            acc[1][0]=fmaf(av.y,bv.x,acc[1][0]); acc[1][1]=fmaf(av.y,bv.y,acc[1][1]);
            acc[1][2]=fmaf(av.y,bv.z,acc[1][2]); acc[1][3]=fmaf(av.y,bv.w,acc[1][3]);
            acc[2][0]=fmaf(av.z,bv.x,acc[2][0]); acc[2][1]=fmaf(av.z,bv.y,acc[2][1]);
            acc[2][2]=fmaf(av.z,bv.z,acc[2][2]); acc[2][3]=fmaf(av.z,bv.w,acc[2][3]);
            acc[3][0]=fmaf(av.w,bv.x,acc[3][0]); acc[3][1]=fmaf(av.w,bv.y,acc[3][1]);
            acc[3][2]=fmaf(av.w,bv.z,acc[3][2]); acc[3][3]=fmaf(av.w,bv.w,acc[3][3]);
        }
        __syncthreads();
    }
    #pragma unroll
    for (int i = 0; i < 4; i++) {
        int tn = tn0 + tr * 4 + i;
        #pragma unroll
        for (int j = 0; j < 4; j++) {
            int a = a0 + tc * 4 + j;
            if (a < A)
                g_Kproj[(size_t)(l * T * NB + tn) * A + a] = acc[i][j] + Kb[l * A + a];
        }
    }
}

// ---------------- GRU phase helper (in-warp split-K, interleaved k) ----------------
template <int KINP>
__device__ __forceinline__ void gru_phase(
    const float* __restrict__ Wih, const float* __restrict__ Whh,
    const float* __restrict__ bih, const float* __restrict__ bhh,
    const float* __restrict__ xin, const float* __restrict__ hin,
    float* __restrict__ hout, int gtid, int nthr)
{
    for (int t = gtid; t < H * 16 * 8; t += nthr) {
        int ks = t & 7;
        int nq = (t >> 3) & 15;
        int j  = t >> 7;
        int n0 = nq * 4;
        const float* wr = Wih + (size_t)j * KINP;
        const float* wz = wr + (size_t)H * KINP;
        const float* wn = wz + (size_t)H * KINP;
        const float* vr = Whh + (size_t)j * H;
        const float* vz = vr + (size_t)H * H;
        const float* vn = vz + (size_t)H * H;
        float ar[4] = {0,0,0,0}, az[4] = {0,0,0,0};
        float ai[4] = {0,0,0,0}, ah[4] = {0,0,0,0};
        // x segment (interleaved split-K: lane group covers k = ks*4 + 32*i)
        for (int k = ks * 4; k < KINP; k += 32) {
            float4 wR = *(const float4*)(wr + k);
            float4 wZ = *(const float4*)(wz + k);
            float4 wN = *(const float4*)(wn + k);
            float4 x0 = *(const float4*)(&xin[(k + 0) * NB + n0]);
            float4 x1 = *(const float4*)(&xin[(k + 1) * NB + n0]);
            float4 x2 = *(const float4*)(&xin[(k + 2) * NB + n0]);
            float4 x3 = *(const float4*)(&xin[(k + 3) * NB + n0]);
            ar[0]=fmaf(wR.x,x0.x,ar[0]); ar[1]=fmaf(wR.x,x0.y,ar[1]); ar[2]=fmaf(wR.x,x0.z,ar[2]); ar[3]=fmaf(wR.x,x0.w,ar[3]);
            ar[0]=fmaf(wR.y,x1.x,ar[0]); ar[1]=fmaf(wR.y,x1.y,ar[1]); ar[2]=fmaf(wR.y,x1.z,ar[2]); ar[3]=fmaf(wR.y,x1.w,ar[3]);
            ar[0]=fmaf(wR.z,x2.x,ar[0]); ar[1]=fmaf(wR.z,x2.y,ar[1]); ar[2]=fmaf(wR.z,x2.z,ar[2]); ar[3]=fmaf(wR.z,x2.w,ar[3]);
            ar[0]=fmaf(wR.w,x3.x,ar[0]); ar[1]=fmaf(wR.w,x3.y,ar[1]); ar[2]=fmaf(wR.w,x3.z,ar[2]); ar[3]=fmaf(wR.w,x3.w,ar[3]);
            az[0]=fmaf(wZ.x,x0.x,az[0]); az[1]=fmaf(wZ.x,x0.y,az[1]); az[2]=fmaf(wZ.x,x0.z,az[2]); az[3]=fmaf(wZ.x,x0.w,az[3]);
            az[0]=fmaf(wZ.y,x1.x,az[0]); az[1]=fmaf(wZ.y,x1.y,az[1]); az[2]=fmaf(wZ.y,x1.z,az[2]); az[3]=fmaf(wZ.y,x1.w,az[3]);
            az[0]=fmaf(wZ.z,x2.x,az[0]); az[1]=fmaf(wZ.z,x2.y,az[1]); az[2]=fmaf(wZ.z,x2.z,az[2]); az[3]=fmaf(wZ.z,x2.w,az[3]);
            az[0]=fmaf(wZ.w,x3.x,az[0]); az[1]=fmaf(wZ.w,x3.y,az[1]); az[2]=fmaf(wZ.w,x3.z,az[2]); az[3]=fmaf(wZ.w,x3.w,az[3]);
            ai[0]=fmaf(wN.x,x0.x,ai[0]); ai[1]=fmaf(wN.x,x0.y,ai[1]); ai[2]=fmaf(wN.x,x0.z,ai[2]); ai[3]=fmaf(wN.x,x0.w,ai[3]);
            ai[0]=fmaf(wN.y,x1.x,ai[0]); ai[1]=fmaf(wN.y,x1.y,ai[1]); ai[2]=fmaf(wN.y,x1.z,ai[2]); ai[3]=fmaf(wN.y,x1.w,ai[3]);
            ai[0]=fmaf(wN.z,x2.x,ai[0]); ai[1]=fmaf(wN.z,x2.y,ai[1]); ai[2]=fmaf(wN.z,x2.z,ai[2]); ai[3]=fmaf(wN.z,x2.w,ai[3]);
            ai[0]=fmaf(wN.w,x3.x,ai[0]); ai[1]=fmaf(wN.w,x3.y,ai[1]); ai[2]=fmaf(wN.w,x3.z,ai[2]); ai[3]=fmaf(wN.w,x3.w,ai[3]);
        }
        // h segment
        for (int k = ks * 4; k < H; k += 32) {
            float4 wR = *(const float4*)(vr + k);
            float4 wZ = *(const float4*)(vz + k);
            float4 wN = *(const float4*)(vn + k);
            float4 x0 = *(const float4*)(&hin[(k + 0) * NB + n0]);
            float4 x1 = *(const float4*)(&hin[(k + 1) * NB + n0]);
            float4 x2 = *(const float4*)(&hin[(k + 2) * NB + n0]);
            float4 x3 = *(const float4*)(&hin[(k + 3) * NB + n0]);
            ar[0]=fmaf(wR.x,x0.x,ar[0]); ar[1]=fmaf(wR.x,x0.y,ar[1]); ar[2]=fmaf(wR.x,x0.z,ar[2]); ar[3]=fmaf(wR.x,x0.w,ar[3]);
            ar[0]=fmaf(wR.y,x1.x,ar[0]); ar[1]=fmaf(wR.y,x1.y,ar[1]); ar[2]=fmaf(wR.y,x1.z,ar[2]); ar[3]=fmaf(wR.y,x1.w,ar[3]);
            ar[0]=fmaf(wR.z,x2.x,ar[0]); ar[1]=fmaf(wR.z,x2.y,ar[1]); ar[2]=fmaf(wR.z,x2.z,ar[2]); ar[3]=fmaf(wR.z,x2.w,ar[3]);
            ar[0]=fmaf(wR.w,x3.x,ar[0]); ar[1]=fmaf(wR.w,x3.y,ar[1]); ar[2]=fmaf(wR.w,x3.z,ar[2]); ar[3]=fmaf(wR.w,x3.w,ar[3]);
            az[0]=fmaf(wZ.x,x0.x,az[0]); az[1]=fmaf(wZ.x,x0.y,az[1]); az[2]=fmaf(wZ.x,x0.z,az[2]); az[3]=fmaf(wZ.x,x0.w,az[3]);
            az[0]=fmaf(wZ.y,x1.x,az[0]); az[1]=fmaf(wZ.y,x1.y,az[1]); az[2]=fmaf(wZ.y,x1.z,az[2]); az[3]=fmaf(wZ.y,x1.w,az[3]);
            az[0]=fmaf(wZ.z,x2.x,az[0]); az[1]=fmaf(wZ.z,x2.y,az[1]); az[2]=fmaf(wZ.z,x2.z,az[2]); az[3]=fmaf(wZ.z,x2.w,az[3]);
            az[0]=fmaf(wZ.w,x3.x,az[0]); az[1]=fmaf(wZ.w,x3.y,az[1]); az[2]=fmaf(wZ.w,x3.z,az[2]); az[3]=fmaf(wZ.w,x3.w,az[3]);
            ah[0]=fmaf(wN.x,x0.x,ah[0]); ah[1]=fmaf(wN.x,x0.y,ah[1]); ah[2]=fmaf(wN.x,x0.z,ah[2]); ah[3]=fmaf(wN.x,x0.w,ah[3]);
            ah[0]=fmaf(wN.y,x1.x,ah[0]); ah[1]=fmaf(wN.y,x1.y,ah[1]); ah[2]=fmaf(wN.y,x1.z,ah[2]); ah[3]=fmaf(wN.y,x1.w,ah[3]);
            ah[0]=fmaf(wN.z,x2.x,ah[0]); ah[1]=fmaf(wN.z,x2.y,ah[1]); ah[2]=fmaf(wN.z,x2.z,ah[2]); ah[3]=fmaf(wN.z,x2.w,ah[3]);
            ah[0]=fmaf(wN.w,x3.x,ah[0]); ah[1]=fmaf(wN.w,x3.y,ah[1]); ah[2]=fmaf(wN.w,x3.z,ah[2]); ah[3]=fmaf(wN.w,x3.w,ah[3]);
        }
        // in-warp split-K reduce over 8 lanes
        #pragma unroll
        for (int off = 4; off >= 1; off >>= 1) {
            #pragma unroll
            for (int i = 0; i < 4; i++) {
                ar[i] += __shfl_xor_sync(0xFFFFFFFFu, ar[i], off, 8);
                az[i] += __shfl_xor_sync(0xFFFFFFFFu, az[i], off, 8);
                ai[i] += __shfl_xor_sync(0xFFFFFFFFu, ai[i], off, 8);
                ah[i] += __shfl_xor_sync(0xFFFFFFFFu, ah[i], off, 8);
            }
        }
        if (ks == 0) {
            float br = bih[j] + bhh[j];
            float bz = bih[H + j] + bhh[H + j];
            float bi = bih[2 * H + j];
            float bh = bhh[2 * H + j];
            #pragma unroll
            for (int i = 0; i < 4; i++) {
                float r = sigmoid_fast(ar[i] + br);
                float z = sigmoid_fast(az[i] + bz);
                float nn = tanh_fast(ai[i] + bi + r * (ah[i] + bh));
                float hp = hin[j * NB + n0 + i];
                hout[j * NB + n0 + i] = fmaf(z, hp - nn, nn);
            }
        }
    }
}

// ---------------- the persistent decode kernel ----------------
__global__ void __launch_bounds__(512, 1)
decode_all(const float* __restrict__ eo, const int* __restrict__ targets,
           const float* __restrict__ embW,
           const float* __restrict__ Qw, const float* __restrict__ Qb,
           const float* __restrict__ Vw, const float* __restrict__ Vb,
           const float* __restrict__ Wih0, const float* __restrict__ Whh0,
           const float* __restrict__ bih0, const float* __restrict__ bhh0,
           const float* __restrict__ Wih1, const float* __restrict__ Whh1,
           const float* __restrict__ bih1, const float* __restrict__ bhh1,
           const float* __restrict__ Pw0, const float* __restrict__ Pb0,
           const float* __restrict__ Pw1, const float* __restrict__ Pb1,
           float* __restrict__ out)
{
    const int nb   = gridDim.x;
    const int tid  = threadIdx.x;
    const int gtid = blockIdx.x * 512 + tid;
    const int nthr = nb * 512;
    const int lane = tid & 31;

    __shared__ float smw[LT];
    __shared__ float sred[32];

    for (int s = 0; s < S; s++) {
        const int cur = s & 1;
        const int nxt = cur ^ 1;

        // ---- phase 1: qproj (tasks (l,a,nq) x ks8) ----
        for (int t = gtid; t < L * A * 16 * 8; t += nthr) {
            int ks = t & 7;
            int nq = (t >> 3) & 15;
            int r  = t >> 7;                 // l*A + a
            int a  = r % A, l = r / A;
            int n0 = nq * 4;
            const float* hp = g_h[cur][l];
            const float* w  = Qw + (size_t)r * H;
            float a0 = 0.f, a1 = 0.f, a2 = 0.f, a3 = 0.f;
            for (int k = ks * 4; k < H; k += 32) {
                float4 wv = *(const float4*)(w + k);
                float4 h0 = *(const float4*)(&hp[(k + 0) * NB + n0]);
                float4 h1 = *(const float4*)(&hp[(k + 1) * NB + n0]);
                float4 h2 = *(const float4*)(&hp[(k + 2) * NB + n0]);
                float4 h3 = *(const float4*)(&hp[(k + 3) * NB + n0]);
                a0=fmaf(wv.x,h0.x,a0); a1=fmaf(wv.x,h0.y,a1); a2=fmaf(wv.x,h0.z,a2); a3=fmaf(wv.x,h0.w,a3);
                a0=fmaf(wv.y,h1.x,a0); a1=fmaf(wv.y,h1.y,a1); a2=fmaf(wv.y,h1.z,a2); a3=fmaf(wv.y,h1.w,a3);
                a0=fmaf(wv.z,h2.x,a0); a1=fmaf(wv.z,h2.y,a1); a2=fmaf(wv.z,h2.z,a2); a3=fmaf(wv.z,h2.w,a3);
                a0=fmaf(wv.w,h3.x,a0); a1=fmaf(wv.w,h3.y,a1); a2=fmaf(wv.w,h3.z,a2); a3=fmaf(wv.w,h3.w,a3);
            }
            #pragma unroll
            for (int off = 4; off >= 1; off >>= 1) {
                a0 += __shfl_xor_sync(0xFFFFFFFFu, a0, off, 8);
                a1 += __shfl_xor_sync(0xFFFFFFFFu, a1, off, 8);
                a2 += __shfl_xor_sync(0xFFFFFFFFu, a2, off, 8);
                a3 += __shfl_xor_sync(0xFFFFFFFFu, a3, off, 8);
            }
            if (ks == 0) {
                float b = Qb[r];
                g_qproj[((size_t)l * NB + n0 + 0) * A + a] = a0 + b;
                g_qproj[((size_t)l * NB + n0 + 1) * A + a] = a1 + b;
                g_qproj[((size_t)l * NB + n0 + 2) * A + a] = a2 + b;
                g_qproj[((size_t)l * NB + n0 + 3) * A + a] = a3 + b;
            }
        }
        grid_sync(nb);

        // ---- phase 2: scores (warp-tasks (lt, ngroup of 8)) ----
        {
            int gw = gtid >> 5, nw = nthr >> 5;
            for (int wt = gw; wt < LT * 8; wt += nw) {
                int ng = wt & 7;
                int lt = wt >> 3;
                int l  = lt >> 7;            // / T
                int nbase = ng * 8;
                float acc[8] = {0,0,0,0,0,0,0,0};
                for (int i = 0; i < 7; i++) {
                    int a = i * 32 + lane;
                    if (a < A) {
                        float v = Vw[l * A + a];
                        #pragma unroll
                        for (int q = 0; q < 8; q++) {
                            int n = nbase + q;
                            float xq = g_qproj[((size_t)l * NB + n) * A + a]
                                     + g_Kproj[((size_t)lt * NB + n) * A + a];
                            acc[q] = fmaf(v, tanh_fast(xq), acc[q]);
                        }
                    }
                }
                #pragma unroll
                for (int q = 0; q < 8; q++) {
                    #pragma unroll
                    for (int off = 16; off >= 1; off >>= 1)
                        acc[q] += __shfl_down_sync(0xFFFFFFFFu, acc[q], off);
                }
                if (lane == 0) {
                    float vb = Vb[l];
                    #pragma unroll
                    for (int q = 0; q < 8; q++)
                        g_scores[(nbase + q) * LT + lt] = acc[q] + vb;
                }
            }
        }
        grid_sync(nb);

        // ---- phase 3: softmax + context + embedding (block-tasks (n, half)) ----
        for (int bt = blockIdx.x; bt < NB * 2; bt += nb) {
            int n = bt >> 1, half = bt & 1;
            float sc = (tid < LT) ? g_scores[n * LT + tid] : -3.4e38f;
            float m = sc;
            #pragma unroll
            for (int off = 16; off >= 1; off >>= 1)
                m = fmaxf(m, __shfl_xor_sync(0xFFFFFFFFu, m, off));
            if (lane == 0) sred[tid >> 5] = m;
            __syncthreads();
            if (tid < 16) {
                float v = sred[tid];
                #pragma unroll
                for (int off = 8; off >= 1; off >>= 1)
                    v = fmaxf(v, __shfl_xor_sync(0xFFFFu, v, off, 16));
                if (tid == 0) sred[0] = v;
            }
            __syncthreads();
            float mx = sred[0];
            float e = (tid < LT) ? __expf(sc - mx) : 0.f;
            float su = e;
            #pragma unroll
            for (int off = 16; off >= 1; off >>= 1)
                su += __shfl_xor_sync(0xFFFFFFFFu, su, off);
            __syncthreads();
            if (lane == 0) sred[tid >> 5] = su;
            __syncthreads();
            if (tid < 16) {
                float v = sred[tid];
                #pragma unroll
                for (int off = 8; off >= 1; off >>= 1)
                    v += __shfl_xor_sync(0xFFFFu, v, off, 16);
                if (tid == 0) sred[0] = v;
            }
            __syncthreads();
            float inv = 1.0f / sred[0];
            if (tid < LT) smw[tid] = e * inv;
            __syncthreads();
            if (tid < 256) {
                int h = half * 256 + tid;
                const float* ep = eo + (size_t)n * H + h;
                float acc = 0.f;
                #pragma unroll 8
                for (int lt2 = 0; lt2 < LT; lt2++)
                    acc = fmaf(smw[lt2], ep[(size_t)lt2 * (NB * H)], acc);
                g_x[(E + h) * NB + n] = acc;
            }
            if (half == 0 && tid < E) {
                int tok = (s == 0) ? 1 : targets[n * S + (s - 1)];
                g_x[tid * NB + n] = fmaxf(embW[(size_t)tok * E + tid], 0.f);
            }
            __syncthreads();
        }
        grid_sync(nb);

        // ---- phase 4: GRU layer 0 ----
        gru_phase<KIN0>(Wih0, Whh0, bih0, bhh0, g_x, g_h[cur][0], g_h[nxt][0], gtid, nthr);
        grid_sync(nb);

        // ---- phase 5: GRU layer 1 ----
        gru_phase<H>(Wih1, Whh1, bih1, bhh1, g_h[nxt][0], g_h[cur][1], g_h[nxt][1], gtid, nthr);
        grid_sync(nb);

        // ---- phase 6: proj (tasks (j,nq) x ks8) ----
        for (int t = gtid; t < H * 16 * 8; t += nthr) {
            int ks = t & 7;
            int nq = (t >> 3) & 15;
            int j  = t >> 7;
            int n0 = nq * 4;
            const float* w = Pw0 + (size_t)j * H;
            const float* h1 = g_h[nxt][1];
            float a0 = 0.f, a1 = 0.f, a2 = 0.f, a3 = 0.f;
            for (int k = ks * 4; k < H; k += 32) {
                float4 wv = *(const float4*)(w + k);
                float4 x0 = *(const float4*)(&h1[(k + 0) * NB + n0]);
                float4 x1 = *(const float4*)(&h1[(k + 1) * NB + n0]);
                float4 x2 = *(const float4*)(&h1[(k + 2) * NB + n0]);
                float4 x3 = *(const float4*)(&h1[(k + 3) * NB + n0]);
                a0=fmaf(wv.x,x0.x,a0); a1=fmaf(wv.x,x0.y,a1); a2=fmaf(wv.x,x0.z,a2); a3=fmaf(wv.x,x0.w,a3);
                a0=fmaf(wv.y,x1.x,a0); a1=fmaf(wv.y,x1.y,a1); a2=fmaf(wv.y,x1.z,a2); a3=fmaf(wv.y,x1.w,a3);
                a0=fmaf(wv.z,x2.x,a0); a1=fmaf(wv.z,x2.y,a1); a2=fmaf(wv.z,x2.z,a2); a3=fmaf(wv.z,x2.w,a3);
                a0=fmaf(wv.w,x3.x,a0); a1=fmaf(wv.w,x3.y,a1); a2=fmaf(wv.w,x3.z,a2); a3=fmaf(wv.w,x3.w,a3);
            }
            #pragma unroll
            for (int off = 4; off >= 1; off >>= 1) {
                a0 += __shfl_xor_sync(0xFFFFFFFFu, a0, off, 8);
                a1 += __shfl_xor_sync(0xFFFFFFFFu, a1, off, 8);
                a2 += __shfl_xor_sync(0xFFFFFFFFu, a2, off, 8);
                a3 += __shfl_xor_sync(0xFFFFFFFFu, a3, off, 8);
            }
            if (ks == 0) {
                float b = Pb0[j];
                g_proj[j * NB + n0 + 0] = fmaxf(a0 + b, 0.f);
                g_proj[j * NB + n0 + 1] = fmaxf(a1 + b, 0.f);
                g_proj[j * NB + n0 + 2] = fmaxf(a2 + b, 0.f);
                g_proj[j * NB + n0 + 3] = fmaxf(a3 + b, 0.f);
            }
        }
        grid_sync(nb);

        // ---- phase 7: logits (tasks (v,nq) x ks4) -> out ----
        for (int t = gtid; t < V * 16 * 4; t += nthr) {
            int ks = t & 3;
            int nq = (t >> 2) & 15;
            int v  = t >> 6;
            int n0 = nq * 4;
            const float* w = Pw1 + (size_t)v * H;
            float a0 = 0.f, a1 = 0.f, a2 = 0.f, a3 = 0.f;
            for (int k = ks * 4; k < H; k += 16) {
                float4 wv = *(const float4*)(w + k);
                float4 x0 = *(const float4*)(&g_proj[(k + 0) * NB + n0]);
                float4 x1 = *(const float4*)(&g_proj[(k + 1) * NB + n0]);
                float4 x2 = *(const float4*)(&g_proj[(k + 2) * NB + n0]);
                float4 x3 = *(const float4*)(&g_proj[(k + 3) * NB + n0]);
                a0=fmaf(wv.x,x0.x,a0); a1=fmaf(wv.x,x0.y,a1); a2=fmaf(wv.x,x0.z,a2); a3=fmaf(wv.x,x0.w,a3);
                a0=fmaf(wv.y,x1.x,a0); a1=fmaf(wv.y,x1.y,a1); a2=fmaf(wv.y,x1.z,a2); a3=fmaf(wv.y,x1.w,a3);
                a0=fmaf(wv.z,x2.x,a0); a1=fmaf(wv.z,x2.y,a1); a2=fmaf(wv.z,x2.z,a2); a3=fmaf(wv.z,x2.w,a3);
                a0=fmaf(wv.w,x3.x,a0); a1=fmaf(wv.w,x3.y,a1); a2=fmaf(wv.w,x3.z,a2); a3=fmaf(wv.w,x3.w,a3);
            }
            #pragma unroll
            for (int off = 2; off >= 1; off >>= 1) {
                a0 += __shfl_xor_sync(0xFFFFFFFFu, a0, off, 4);
                a1 += __shfl_xor_sync(0xFFFFFFFFu, a1, off, 4);
                a2 += __shfl_xor_sync(0xFFFFFFFFu, a2, off, 4);
                a3 += __shfl_xor_sync(0xFFFFFFFFu, a3, off, 4);
            }
            if (ks == 0) {
                float b = Pb1[v];
                out[((size_t)(n0 + 0) * S + s) * V + v] = a0 + b;
                out[((size_t)(n0 + 1) * S + s) * V + v] = a1 + b;
                out[((size_t)(n0 + 2) * S + s) * V + v] = a2 + b;
                out[((size_t)(n0 + 3) * S + s) * V + v] = a3 + b;
            }
        }
        grid_sync(nb);
    }
}

// ---------------- launcher ----------------
extern "C" void kernel_launch(void* const* d_in, const int* in_sizes, int n_in,
                              void* d_out, int out_size) {
    const float* eo      = (const float*)d_in[0];
    const float* efs     = (const float*)d_in[1];
    const int*   targets = (const int*)  d_in[2];
    const float* embW    = (const float*)d_in[3];
    const float* Qw      = (const float*)d_in[4];
    const float* Qb      = (const float*)d_in[5];
    const float* Kw      = (const float*)d_in[6];
    const float* Kb      = (const float*)d_in[7];
    const float* Vw      = (const float*)d_in[8];
    const float* Vb      = (const float*)d_in[9];
    const float* Wih0    = (const float*)d_in[10];
    const float* Whh0    = (const float*)d_in[11];
    const float* bih0    = (const float*)d_in[12];
    const float* bhh0    = (const float*)d_in[13];
    const float* Wih1    = (const float*)d_in[14];
    const float* Whh1    = (const float*)d_in[15];
    const float* bih1    = (const float*)d_in[16];
    const float* bhh1    = (const float*)d_in[17];
    const float* Pw0     = (const float*)d_in[18];
    const float* Pb0     = (const float*)d_in[19];
    const float* Pw1     = (const float*)d_in[20];
    const float* Pb1     = (const float*)d_in[21];
    float* out = (float*)d_out;

    int smCount = 148;
    cudaDeviceGetAttribute(&smCount, cudaDevAttrMultiProcessorCount, 0);

    prep_hinit<<<(L * NB * H + 255) / 256, 256>>>(efs);
    kproj_gemm<<<dim3(128, 4, 2), 256>>>(eo, Kw, Kb);
    decode_all<<<smCount, 512>>>(eo, targets, embW, Qw, Qb, Vw, Vb,
                                 Wih0, Whh0, bih0, bhh0,
                                 Wih1, Whh1, bih1, bhh1,
                                 Pw0, Pb0, Pw1, Pb1, out);
}

// round 8
// speedup vs baseline: 2.6185x; 2.6185x over previous
#include <cuda_runtime.h>
#include <cstdint>

#define L  2
#define T  128
#define NB 64      // batch N
#define H  512
#define E  256
#define A  200
#define V  1000
#define S  40
#define LT (L*T)   // 256

// ---------------- scratch (device globals) ----------------
__device__ __align__(16) float g_Kproj[L*T*NB*A];    // (l,t,n,a)
__device__ __align__(16) float g_qproj[L*NB*A];      // (l,n,a)
__device__ __align__(16) float g_scores[NB*LT];      // (n, lt)
__device__ __align__(16) float g_x[(E+H)*NB];        // (k,n)
__device__ __align__(16) float g_h[2][L][H*NB];      // [pingpong][layer][(k,n)]
__device__ __align__(16) float g_proj[H*NB];         // (k,n)

// ---------------- MUFU-free fast math ----------------
__device__ __forceinline__ float fast_rcp(float q) {
    float r = __uint_as_float(0x7EF311C3u - __float_as_uint(q));
    r = r * (2.0f - q * r);
    r = r * (2.0f - q * r);
    r = r * (2.0f - q * r);
    return r;
}

__device__ __forceinline__ float tanh_fast(float x) {
    const float c = 7.99881172180175781f;
    x = fminf(fmaxf(x, -c), c);
    float x2 = x * x;
    float p = fmaf(x2, -2.76076847742355e-16f, 2.00018790482477e-13f);
    p = fmaf(x2, p, -8.60467152213735e-11f);
    p = fmaf(x2, p,  5.12229709037114e-08f);
    p = fmaf(x2, p,  1.48572235717979e-05f);
    p = fmaf(x2, p,  6.37261928875436e-04f);
    p = fmaf(x2, p,  4.89352455891786e-03f);
    p = p * x;
    float q = fmaf(x2, 1.19825839466702e-06f, 1.18534705686654e-04f);
    q = fmaf(x2, q, 2.26843463243900e-03f);
    q = fmaf(x2, q, 4.89352518554385e-03f);
    return p * fast_rcp(q);
}

__device__ __forceinline__ float sigmoid_fast(float x) {
    return fmaf(tanh_fast(0.5f * x), 0.5f, 0.5f);
}

// ---------------- prep kernels (once per launch) ----------------
__global__ void prep_hinit(const float* __restrict__ efs) {
    int i = blockIdx.x * 256 + threadIdx.x;        // over L*NB*H
    if (i >= L * NB * H) return;
    int k = i % H;
    int n = (i / H) % NB;
    int l = i / (NB * H);
    g_h[0][l][k * NB + n] = efs[i];
}

__global__ void kproj_gemm(const float* __restrict__ eo,
                           const float* __restrict__ Kw,
                           const float* __restrict__ Kb) {
    const int l   = blockIdx.z;
    const int tn0 = blockIdx.x * 64;
    const int a0  = blockIdx.y * 64;
    const float* Ab = eo + (size_t)l * (T * NB) * H;
    const float* Bb = Kw + (size_t)l * A * H;
    __shared__ float As[16][64];
    __shared__ float Bs[16][64];
    const int tid = threadIdx.x;
    const int tr = tid >> 4, tc = tid & 15;
    const int lr = tid >> 2;
    const int lk = (tid & 3) * 4;
    float acc[4][4];
    #pragma unroll
    for (int i = 0; i < 4; i++)
        #pragma unroll
        for (int j = 0; j < 4; j++) acc[i][j] = 0.0f;

    for (int k0 = 0; k0 < H; k0 += 16) {
        float4 a4 = *reinterpret_cast<const float4*>(&Ab[(size_t)(tn0 + lr) * H + k0 + lk]);
        As[lk + 0][lr] = a4.x; As[lk + 1][lr] = a4.y;
        As[lk + 2][lr] = a4.z; As[lk + 3][lr] = a4.w;
        float4 b4 = make_float4(0.f, 0.f, 0.f, 0.f);
        if (a0 + lr < A)
            b4 = *reinterpret_cast<const float4*>(&Bb[(size_t)(a0 + lr) * H + k0 + lk]);
        Bs[lk + 0][lr] = b4.x; Bs[lk + 1][lr] = b4.y;
        Bs[lk + 2][lr] = b4.z; Bs[lk + 3][lr] = b4.w;
        __syncthreads();
        #pragma unroll
        for (int kk = 0; kk < 16; kk++) {
            float4 av = *reinterpret_cast<const float4*>(&As[kk][tr * 4]);
            float4 bv = *reinterpret_cast<const float4*>(&Bs[kk][tc * 4]);
            acc[0][0]=fmaf(av.x,bv.x,acc[0][0]); acc[0][1]=fmaf(av.x,bv.y,acc[0][1]);
            acc[0][2]=fmaf(av.x,bv.z,acc[0][2]); acc[0][3]=fmaf(av.x,bv.w,acc[0][3]);
            acc[1][0]=fmaf(av.y,bv.x,acc[1][0]); acc[1][1]=fmaf(av.y,bv.y,acc[1][1]);
            acc[1][2]=fmaf(av.y,bv.z,acc[1][2]); acc[1][3]=fmaf(av.y,bv.w,acc[1][3]);
            acc[2][0]=fmaf(av.z,bv.x,acc[2][0]); acc[2][1]=fmaf(av.z,bv.y,acc[2][1]);
            acc[2][2]=fmaf(av.z,bv.z,acc[2][2]); acc[2][3]=fmaf(av.z,bv.w,acc[2][3]);
            acc[3][0]=fmaf(av.w,bv.x,acc[3][0]); acc[3][1]=fmaf(av.w,bv.y,acc[3][1]);
            acc[3][2]=fmaf(av.w,bv.z,acc[3][2]); acc[3][3]=fmaf(av.w,bv.w,acc[3][3]);
        }
        __syncthreads();
    }
    #pragma unroll
    for (int i = 0; i < 4; i++) {
        int tn = tn0 + tr * 4 + i;
        #pragma unroll
        for (int j = 0; j < 4; j++) {
            int a = a0 + tc * 4 + j;
            if (a < A)
                g_Kproj[(size_t)(l * T * NB + tn) * A + a] = acc[i][j] + Kb[l * A + a];
        }
    }
}

// ============ row-per-block GEMM kernels (weights read ONCE, smem broadcast) ====

// Single-row dot helper: warp w covers k-range [w*kx, (w+1)*kx); lane = (half, ln);
// half covers kx/2; chunks of 16 staged to smem then broadcast.
// Each lane accumulates 4 n-columns. Result: sacc[16 ws][64 n] partials.

// qproj: block (a, l). K=512. out g_qproj[(l*NB+n)*A+a] = dot + Qb.
__global__ void __launch_bounds__(256, 4)
qproj_row(const float* __restrict__ Qw, const float* __restrict__ Qb, int cur) {
    __shared__ float sw[8][2][16];
    __shared__ float sacc[16][64];
    const int a = blockIdx.x, l = blockIdx.y;
    const int tid = threadIdx.x;
    const int w = tid >> 5, lane = tid & 31;
    const int half = lane >> 4, ln = lane & 15;
    const int n0 = ln * 4;
    const float* __restrict__ wrow = Qw + ((size_t)(l * A + a)) * H;
    const float* __restrict__ xin = g_h[cur][l];

    float acc[4] = {0.f, 0.f, 0.f, 0.f};
    const int kx = H / 8;                 // 64
    const int kb = w * kx + half * (kx / 2);
    #pragma unroll
    for (int kc = 0; kc < kx / 2; kc += 16) {
        sw[w][half][ln] = wrow[kb + kc + ln];
        __syncwarp();
        #pragma unroll
        for (int c = 0; c < 16; c++) {
            float wv = sw[w][half][c];
            float4 xv = *(const float4*)&xin[(kb + kc + c) * NB + n0];
            acc[0] = fmaf(wv, xv.x, acc[0]);
            acc[1] = fmaf(wv, xv.y, acc[1]);
            acc[2] = fmaf(wv, xv.z, acc[2]);
            acc[3] = fmaf(wv, xv.w, acc[3]);
        }
        __syncwarp();
    }
    *(float4*)&sacc[w * 2 + half][n0] = make_float4(acc[0], acc[1], acc[2], acc[3]);
    __syncthreads();
    if (tid < 64) {
        float s = 0.f;
        #pragma unroll
        for (int ws = 0; ws < 16; ws++) s += sacc[ws][tid];
        g_qproj[((size_t)l * NB + tid) * A + a] = s + Qb[l * A + a];
    }
}

// GRU row: block j (0..511). Fused x-part (3 gate rows of Wih) + h-part (3 of Whh),
// in-block split-K reduce, gate nonlinearity, writes h_new. KIN = 768 or 512.
template <int KIN>
__global__ void __launch_bounds__(256, 3)
gru_row(const float* __restrict__ Wih, const float* __restrict__ Whh,
        const float* __restrict__ bih, const float* __restrict__ bhh,
        int cur, int layer) {
    __shared__ float sw[8][2][3][16];
    __shared__ float sacc[4][16][64];
    __shared__ float sgate[4][64];
    const int j = blockIdx.x;
    const int tid = threadIdx.x;
    const int w = tid >> 5, lane = tid & 31;
    const int half = lane >> 4, ln = lane & 15;
    const int n0 = ln * 4;
    const int nxt = cur ^ 1;

    const float* __restrict__ xin = (layer == 0) ? g_x : g_h[nxt][0];
    const float* __restrict__ hin = g_h[cur][layer];
    float* __restrict__ hout = g_h[nxt][layer];

    const float* __restrict__ wr = Wih + (size_t)j * KIN;
    const float* __restrict__ wz = Wih + (size_t)(H + j) * KIN;
    const float* __restrict__ wn = Wih + (size_t)(2 * H + j) * KIN;
    const float* __restrict__ vr = Whh + (size_t)j * H;
    const float* __restrict__ vz = Whh + (size_t)(H + j) * H;
    const float* __restrict__ vn = Whh + (size_t)(2 * H + j) * H;

    float aR[4] = {0,0,0,0}, aZ[4] = {0,0,0,0};
    float aI[4] = {0,0,0,0}, aHn[4] = {0,0,0,0};

    // ---- x part: per-warp kx = KIN/8; per-half kx/2 (48 or 32), chunks of 16 ----
    {
        const int kx = KIN / 8;
        const int kb = w * kx + half * (kx / 2);
        for (int kc = 0; kc < kx / 2; kc += 16) {
            int k0 = kb + kc;
            sw[w][half][0][ln] = wr[k0 + ln];
            sw[w][half][1][ln] = wz[k0 + ln];
            sw[w][half][2][ln] = wn[k0 + ln];
            __syncwarp();
            #pragma unroll
            for (int c = 0; c < 16; c++) {
                float wRv = sw[w][half][0][c];
                float wZv = sw[w][half][1][c];
                float wNv = sw[w][half][2][c];
                float4 xv = *(const float4*)&xin[(k0 + c) * NB + n0];
                aR[0]=fmaf(wRv,xv.x,aR[0]); aR[1]=fmaf(wRv,xv.y,aR[1]);
                aR[2]=fmaf(wRv,xv.z,aR[2]); aR[3]=fmaf(wRv,xv.w,aR[3]);
                aZ[0]=fmaf(wZv,xv.x,aZ[0]); aZ[1]=fmaf(wZv,xv.y,aZ[1]);
                aZ[2]=fmaf(wZv,xv.z,aZ[2]); aZ[3]=fmaf(wZv,xv.w,aZ[3]);
                aI[0]=fmaf(wNv,xv.x,aI[0]); aI[1]=fmaf(wNv,xv.y,aI[1]);
                aI[2]=fmaf(wNv,xv.z,aI[2]); aI[3]=fmaf(wNv,xv.w,aI[3]);
            }
            __syncwarp();
        }
    }
    // ---- h part: per-warp 64 k, per-half 32, chunks of 16 ----
    {
        const int kb = w * (H / 8) + half * (H / 16);
        #pragma unroll
        for (int kc = 0; kc < H / 16; kc += 16) {
            int k0 = kb + kc;
            sw[w][half][0][ln] = vr[k0 + ln];
            sw[w][half][1][ln] = vz[k0 + ln];
            sw[w][half][2][ln] = vn[k0 + ln];
            __syncwarp();
            #pragma unroll
            for (int c = 0; c < 16; c++) {
                float wRv = sw[w][half][0][c];
                float wZv = sw[w][half][1][c];
                float wNv = sw[w][half][2][c];
                float4 xv = *(const float4*)&hin[(k0 + c) * NB + n0];
                aR[0]=fmaf(wRv,xv.x,aR[0]); aR[1]=fmaf(wRv,xv.y,aR[1]);
                aR[2]=fmaf(wRv,xv.z,aR[2]); aR[3]=fmaf(wRv,xv.w,aR[3]);
                aZ[0]=fmaf(wZv,xv.x,aZ[0]); aZ[1]=fmaf(wZv,xv.y,aZ[1]);
                aZ[2]=fmaf(wZv,xv.z,aZ[2]); aZ[3]=fmaf(wZv,xv.w,aZ[3]);
                aHn[0]=fmaf(wNv,xv.x,aHn[0]); aHn[1]=fmaf(wNv,xv.y,aHn[1]);
                aHn[2]=fmaf(wNv,xv.z,aHn[2]); aHn[3]=fmaf(wNv,xv.w,aHn[3]);
            }
            __syncwarp();
        }
    }
    const int ws = w * 2 + half;
    *(float4*)&sacc[0][ws][n0] = make_float4(aR[0], aR[1], aR[2], aR[3]);
    *(float4*)&sacc[1][ws][n0] = make_float4(aZ[0], aZ[1], aZ[2], aZ[3]);
    *(float4*)&sacc[2][ws][n0] = make_float4(aI[0], aI[1], aI[2], aI[3]);
    *(float4*)&sacc[3][ws][n0] = make_float4(aHn[0], aHn[1], aHn[2], aHn[3]);
    __syncthreads();
    {
        int g = tid >> 6, n = tid & 63;
        float s = 0.f;
        #pragma unroll
        for (int ws2 = 0; ws2 < 16; ws2++) s += sacc[g][ws2][n];
        sgate[g][n] = s;
    }
    __syncthreads();
    if (tid < 64) {
        float br = bih[j] + bhh[j];
        float bz = bih[H + j] + bhh[H + j];
        float bi = bih[2 * H + j];
        float bh = bhh[2 * H + j];
        float r = sigmoid_fast(sgate[0][tid] + br);
        float z = sigmoid_fast(sgate[1][tid] + bz);
        float nn = tanh_fast(sgate[2][tid] + bi + r * (sgate[3][tid] + bh));
        float hp = hin[j * NB + tid];
        hout[j * NB + tid] = fmaf(z, hp - nn, nn);
    }
}

// proj: block j (0..511). K=512, input h[nxt][1], relu, out g_proj (coalesced row).
__global__ void __launch_bounds__(256, 4)
proj_row(const float* __restrict__ Pw0, const float* __restrict__ Pb0, int cur) {
    __shared__ float sw[8][2][16];
    __shared__ float sacc[16][64];
    const int j = blockIdx.x;
    const int tid = threadIdx.x;
    const int w = tid >> 5, lane = tid & 31;
    const int half = lane >> 4, ln = lane & 15;
    const int n0 = ln * 4;
    const float* __restrict__ wrow = Pw0 + (size_t)j * H;
    const float* __restrict__ xin = g_h[cur ^ 1][1];

    float acc[4] = {0.f, 0.f, 0.f, 0.f};
    const int kb = w * (H / 8) + half * (H / 16);
    #pragma unroll
    for (int kc = 0; kc < H / 16; kc += 16) {
        sw[w][half][ln] = wrow[kb + kc + ln];
        __syncwarp();
        #pragma unroll
        for (int c = 0; c < 16; c++) {
            float wv = sw[w][half][c];
            float4 xv = *(const float4*)&xin[(kb + kc + c) * NB + n0];
            acc[0] = fmaf(wv, xv.x, acc[0]);
            acc[1] = fmaf(wv, xv.y, acc[1]);
            acc[2] = fmaf(wv, xv.z, acc[2]);
            acc[3] = fmaf(wv, xv.w, acc[3]);
        }
        __syncwarp();
    }
    *(float4*)&sacc[w * 2 + half][n0] = make_float4(acc[0], acc[1], acc[2], acc[3]);
    __syncthreads();
    if (tid < 64) {
        float s = 0.f;
        #pragma unroll
        for (int ws = 0; ws < 16; ws++) s += sacc[ws][tid];
        g_proj[j * NB + tid] = fmaxf(s + Pb0[j], 0.f);
    }
}

// logits: block v (0..999). K=512, input g_proj, out[n][s][v].
__global__ void __launch_bounds__(256, 4)
logits_row(const float* __restrict__ Pw1, const float* __restrict__ Pb1,
           float* __restrict__ out, int s) {
    __shared__ float sw[8][2][16];
    __shared__ float sacc[16][64];
    const int v = blockIdx.x;
    const int tid = threadIdx.x;
    const int w = tid >> 5, lane = tid & 31;
    const int half = lane >> 4, ln = lane & 15;
    const int n0 = ln * 4;
    const float* __restrict__ wrow = Pw1 + (size_t)v * H;

    float acc[4] = {0.f, 0.f, 0.f, 0.f};
    const int kb = w * (H / 8) + half * (H / 16);
    #pragma unroll
    for (int kc = 0; kc < H / 16; kc += 16) {
        sw[w][half][ln] = wrow[kb + kc + ln];
        __syncwarp();
        #pragma unroll
        for (int c = 0; c < 16; c++) {
            float wv = sw[w][half][c];
            float4 xv = *(const float4*)&g_proj[(kb + kc + c) * NB + n0];
            acc[0] = fmaf(wv, xv.x, acc[0]);
            acc[1] = fmaf(wv, xv.y, acc[1]);
            acc[2] = fmaf(wv, xv.z, acc[2]);
            acc[3] = fmaf(wv, xv.w, acc[3]);
        }
        __syncwarp();
    }
    *(float4*)&sacc[w * 2 + half][n0] = make_float4(acc[0], acc[1], acc[2], acc[3]);
    __syncthreads();
    if (tid < 64) {
        float sum = 0.f;
        #pragma unroll
        for (int ws = 0; ws < 16; ws++) sum += sacc[ws][tid];
        out[((size_t)tid * S + s) * V + v] = sum + Pb1[v];
    }
}

// ---------------- scores & softmax/context (from R5, single qproj buffer) -------
__global__ void scores_v3(const float* __restrict__ Vw,
                          const float* __restrict__ Vb) {
    int t = blockIdx.x, l = blockIdx.y;
    int warp = threadIdx.x >> 5, lane = threadIdx.x & 31;
    int lt = l * T + t;
    const float* vw = Vw + l * A;
    float vb = Vb[l];

    int n0 = warp, n1 = warp + 16, n2 = warp + 32, n3 = warp + 48;
    const float* kp0 = g_Kproj + (size_t)(lt * NB + n0) * A;
    const float* kp1 = g_Kproj + (size_t)(lt * NB + n1) * A;
    const float* kp2 = g_Kproj + (size_t)(lt * NB + n2) * A;
    const float* kp3 = g_Kproj + (size_t)(lt * NB + n3) * A;
    const float* qp = g_qproj + (size_t)l * NB * A;

    float a0 = 0.f, a1 = 0.f, a2 = 0.f, a3 = 0.f;
    for (int a = lane; a < A; a += 32) {
        float v = vw[a];
        a0 = fmaf(v, tanh_fast(qp[n0 * A + a] + kp0[a]), a0);
        a1 = fmaf(v, tanh_fast(qp[n1 * A + a] + kp1[a]), a1);
        a2 = fmaf(v, tanh_fast(qp[n2 * A + a] + kp2[a]), a2);
        a3 = fmaf(v, tanh_fast(qp[n3 * A + a] + kp3[a]), a3);
    }
    #pragma unroll
    for (int o = 16; o > 0; o >>= 1) {
        a0 += __shfl_down_sync(0xFFFFFFFFu, a0, o);
        a1 += __shfl_down_sync(0xFFFFFFFFu, a1, o);
        a2 += __shfl_down_sync(0xFFFFFFFFu, a2, o);
        a3 += __shfl_down_sync(0xFFFFFFFFu, a3, o);
    }
    if (lane == 0) {
        g_scores[n0 * LT + lt] = a0 + vb;
        g_scores[n1 * LT + lt] = a1 + vb;
        g_scores[n2 * LT + lt] = a2 + vb;
        g_scores[n3 * LT + lt] = a3 + vb;
    }
}

__global__ void context_kernel(const float* __restrict__ eo,
                               const float* __restrict__ embW,
                               const int* __restrict__ targets, int s) {
    __shared__ float w[LT];
    __shared__ float red[128];
    int n = blockIdx.y;
    int hc = blockIdx.x;
    int tid = threadIdx.x;

    float s0 = g_scores[n * LT + tid];
    float s1 = g_scores[n * LT + tid + 128];
    red[tid] = fmaxf(s0, s1);
    __syncthreads();
    #pragma unroll
    for (int o = 64; o > 0; o >>= 1) {
        if (tid < o) red[tid] = fmaxf(red[tid], red[tid + o]);
        __syncthreads();
    }
    float mx = red[0];
    __syncthreads();
    float e0 = __expf(s0 - mx), e1 = __expf(s1 - mx);
    red[tid] = e0 + e1;
    __syncthreads();
    #pragma unroll
    for (int o = 64; o > 0; o >>= 1) {
        if (tid < o) red[tid] += red[tid + o];
        __syncthreads();
    }
    float inv = 1.0f / red[0];
    w[tid] = e0 * inv;
    w[tid + 128] = e1 * inv;
    __syncthreads();

    int h = hc * 128 + tid;
    const float* eop = eo + (size_t)n * H + h;
    float acc = 0.f;
    #pragma unroll 16
    for (int lt = 0; lt < LT; lt++)
        acc = fmaf(w[lt], eop[(size_t)lt * (NB * H)], acc);
    g_x[(E + h) * NB + n] = acc;

    if (hc == 0) {
        int tok = (s == 0) ? 1 : targets[n * S + (s - 1)];
        for (int e = tid; e < E; e += 128)
            g_x[e * NB + n] = fmaxf(embW[tok * E + e], 0.0f);
    }
}

// ---------------- launcher ----------------
extern "C" void kernel_launch(void* const* d_in, const int* in_sizes, int n_in,
                              void* d_out, int out_size) {
    const float* eo      = (const float*)d_in[0];
    const float* efs     = (const float*)d_in[1];
    const int*   targets = (const int*)  d_in[2];
    const float* embW    = (const float*)d_in[3];
    const float* Qw      = (const float*)d_in[4];
    const float* Qb      = (const float*)d_in[5];
    const float* Kw      = (const float*)d_in[6];
    const float* Kb      = (const float*)d_in[7];
    const float* Vw      = (const float*)d_in[8];
    const float* Vb      = (const float*)d_in[9];
    const float* Wih0    = (const float*)d_in[10];
    const float* Whh0    = (const float*)d_in[11];
    const float* bih0    = (const float*)d_in[12];
    const float* bhh0    = (const float*)d_in[13];
    const float* Wih1    = (const float*)d_in[14];
    const float* Whh1    = (const float*)d_in[15];
    const float* bih1    = (const float*)d_in[16];
    const float* bhh1    = (const float*)d_in[17];
    const float* Pw0     = (const float*)d_in[18];
    const float* Pb0     = (const float*)d_in[19];
    const float* Pw1     = (const float*)d_in[20];
    const float* Pb1     = (const float*)d_in[21];
    float* out = (float*)d_out;

    prep_hinit<<<(L * NB * H + 255) / 256, 256>>>(efs);
    kproj_gemm<<<dim3(128, 4, 2), 256>>>(eo, Kw, Kb);

    for (int s = 0; s < S; s++) {
        int cur = s & 1;
        qproj_row<<<dim3(A, L), 256>>>(Qw, Qb, cur);
        scores_v3<<<dim3(T, L), 512>>>(Vw, Vb);
        context_kernel<<<dim3(4, NB), 128>>>(eo, embW, targets, s);
        gru_row<E + H><<<H, 256>>>(Wih0, Whh0, bih0, bhh0, cur, 0);
        gru_row<H><<<H, 256>>>(Wih1, Whh1, bih1, bhh1, cur, 1);
        proj_row<<<H, 256>>>(Pw0, Pb0, cur);
        logits_row<<<V, 256>>>(Pw1, Pb1, out, s);
    }
}